// round 3
// baseline (speedup 1.0000x reference)
#include <cuda_runtime.h>
#include <cstdint>
#include <cstddef>

// RWKV time-mix token-shift block, fp32 baseline.
// out = concat(x_kwvrg[B,S,5,D], new_state[B,66,D])

#define S_LEN 2048
#define D_DIM 2048
#define NST   66      // 2 + HEAD_SIZE
#define NL    160     // LoRA width

// scratch: tanh(xm @ W1), [B*S, 160]
__device__ float g_xxx[8192 * NL];

// ---------------------------------------------------------------------------
// Kernel 1: fused token-shift mix + GEMM1 + tanh
//   xm[r,k] = x[r,k] + (x[r-1,k] - x[r,k]) * tmx[k]   (row -1 -> state[:,i1])
//   g_xxx[r,j] = tanh( sum_k xm[r,k] * W1[k,j] )
// Block: 64 rows x 160 cols, 256 threads, thread tile 8x5, K-tile 16.
// ---------------------------------------------------------------------------
__global__ __launch_bounds__(256) void gemm1_tanh_kernel(
    const float* __restrict__ x, const float* __restrict__ state,
    const float* __restrict__ tmx, const float* __restrict__ w1,
    const int* __restrict__ ip)
{
    __shared__ float As[16][65];     // [k][row], padded
    __shared__ float Bs[16][NL];     // [k][col]

    const int R0 = blockIdx.x * 64;
    const int b  = R0 / S_LEN;
    const int s0 = R0 % S_LEN;
    const int i1 = NST * ip[0] + 1;
    const float* __restrict__ srow = state + ((size_t)b * NST + i1) * D_DIM;

    const int tid = threadIdx.x;
    const int tx  = tid & 31;        // col thread
    const int ty  = tid >> 5;        // row thread
    const int lr  = tid >> 2;        // load: row within tile (0..63)
    const int lk  = (tid & 3) * 4;   // load: k offset (float4)

    float acc[8][5];
#pragma unroll
    for (int i = 0; i < 8; i++)
#pragma unroll
        for (int j = 0; j < 5; j++) acc[i][j] = 0.0f;

    for (int k0 = 0; k0 < D_DIM; k0 += 16) {
        // ---- A tile: compute xm on the fly -------------------------------
        {
            const int gr = R0 + lr;
            const float4 cur = *(const float4*)&x[(size_t)gr * D_DIM + k0 + lk];
            float4 prev;
            if (s0 + lr == 0)
                prev = *(const float4*)&srow[k0 + lk];
            else
                prev = *(const float4*)&x[(size_t)(gr - 1) * D_DIM + k0 + lk];
            const float4 t = *(const float4*)&tmx[k0 + lk];
            As[lk + 0][lr] = cur.x + (prev.x - cur.x) * t.x;
            As[lk + 1][lr] = cur.y + (prev.y - cur.y) * t.y;
            As[lk + 2][lr] = cur.z + (prev.z - cur.z) * t.z;
            As[lk + 3][lr] = cur.w + (prev.w - cur.w) * t.w;
        }
        // ---- B tile: W1[k0..k0+15][0..159] -------------------------------
#pragma unroll
        for (int l = tid; l < 16 * NL; l += 256) {
            const int kk = l / NL, j = l % NL;
            Bs[kk][j] = w1[(size_t)(k0 + kk) * NL + j];
        }
        __syncthreads();

#pragma unroll
        for (int k = 0; k < 16; k++) {
            float a[8], bb[5];
#pragma unroll
            for (int ii = 0; ii < 8; ii++) a[ii] = As[k][ty + 8 * ii];
#pragma unroll
            for (int jj = 0; jj < 5; jj++) bb[jj] = Bs[k][tx + 32 * jj];
#pragma unroll
            for (int ii = 0; ii < 8; ii++)
#pragma unroll
                for (int jj = 0; jj < 5; jj++)
                    acc[ii][jj] = fmaf(a[ii], bb[jj], acc[ii][jj]);
        }
        __syncthreads();
    }

#pragma unroll
    for (int ii = 0; ii < 8; ii++) {
        const size_t r = (size_t)(R0 + ty + 8 * ii);
#pragma unroll
        for (int jj = 0; jj < 5; jj++)
            g_xxx[r * NL + tx + 32 * jj] = tanhf(acc[ii][jj]);
    }
}

// ---------------------------------------------------------------------------
// Kernel 2: GEMM2 + epilogue, fused over the 5 modes.
//   out[r,f,d] = x[r,d] + sx[r,d] * (maa_f[d] + sum_k xxx[r,f*32+k]*W2[f,k,d])
// Block: 64 rows x 256 d-cols, 256 threads, thread tile 8x8 per mode.
// Dynamic smem: xt[65][256] (x incl. prev row), Ws[32][256], Xs[32][65].
// ---------------------------------------------------------------------------
__global__ __launch_bounds__(256, 2) void gemm2_epi_kernel(
    const float* __restrict__ x, const float* __restrict__ state,
    const float* __restrict__ w2,
    const float* __restrict__ mk, const float* __restrict__ mw,
    const float* __restrict__ mv, const float* __restrict__ mr,
    const float* __restrict__ mg,
    const int* __restrict__ ip, float* __restrict__ out)
{
    extern __shared__ float sm[];
    float* xt = sm;                          // 65 * 256
    float* Ws = sm + 65 * 256;               // 32 * 256
    float* Xs = sm + 65 * 256 + 32 * 256;    // 32 * 65 (stride 65: conflict-free)

    const int R0 = blockIdx.x * 64;
    const int d0 = blockIdx.y * 256;
    const int b  = R0 / S_LEN;
    const int s0 = R0 % S_LEN;
    const int i1 = NST * ip[0] + 1;
    const float* __restrict__ srow = state + ((size_t)b * NST + i1) * D_DIM;

    const int tid = threadIdx.x;
    const int tx  = tid & 31;
    const int ty  = tid >> 5;

    // x tile: rows R0-1 .. R0+63 (row -1 from state when s0==0)
    for (int l = tid; l < 65 * 256; l += 256) {
        const int rr = l >> 8, dd = l & 255;
        float v;
        if (rr == 0)
            v = (s0 == 0) ? srow[d0 + dd]
                          : x[(size_t)(R0 - 1) * D_DIM + d0 + dd];
        else
            v = x[(size_t)(R0 + rr - 1) * D_DIM + d0 + dd];
        xt[l] = v;
    }

    for (int f = 0; f < 5; ++f) {
        __syncthreads();   // xt ready (f==0) / previous compute done (f>0)
        for (int l = tid; l < 32 * 256; l += 256)
            Ws[l] = w2[((size_t)f * 32 + (l >> 8)) * D_DIM + d0 + (l & 255)];
        for (int l = tid; l < 64 * 32; l += 256)
            Xs[(l & 31) * 65 + (l >> 5)] =
                g_xxx[(size_t)(R0 + (l >> 5)) * NL + f * 32 + (l & 31)];
        __syncthreads();

        float acc[8][8];
#pragma unroll
        for (int i = 0; i < 8; i++)
#pragma unroll
            for (int j = 0; j < 8; j++) acc[i][j] = 0.0f;

#pragma unroll 8
        for (int k = 0; k < 32; k++) {
            float a[8], w[8];
#pragma unroll
            for (int ri = 0; ri < 8; ri++) a[ri] = Xs[k * 65 + ty + 8 * ri];
#pragma unroll
            for (int dj = 0; dj < 8; dj++) w[dj] = Ws[k * 256 + tx + 32 * dj];
#pragma unroll
            for (int ri = 0; ri < 8; ri++)
#pragma unroll
                for (int dj = 0; dj < 8; dj++)
                    acc[ri][dj] = fmaf(a[ri], w[dj], acc[ri][dj]);
        }

        const float* __restrict__ maa =
            (f == 0) ? mk : (f == 1) ? mw : (f == 2) ? mv : (f == 3) ? mr : mg;

#pragma unroll
        for (int ri = 0; ri < 8; ri++) {
            const int r = ty + 8 * ri;
#pragma unroll
            for (int dj = 0; dj < 8; dj++) {
                const int dd  = tx + 32 * dj;
                const float cur = xt[(r + 1) * 256 + dd];
                const float sx  = xt[r * 256 + dd] - cur;
                const float mvv = maa[d0 + dd];
                out[((size_t)(R0 + r) * 5 + f) * D_DIM + d0 + dd] =
                    cur + sx * (mvv + acc[ri][dj]);
            }
        }
    }
}

// ---------------------------------------------------------------------------
// Kernel 3: new_state = state with row i1 := x[:, S-1, :]
// ---------------------------------------------------------------------------
__global__ void new_state_kernel(
    const float* __restrict__ x, const float* __restrict__ state,
    const int* __restrict__ ip, float* __restrict__ outs, int total)
{
    const int idx = blockIdx.x * blockDim.x + threadIdx.x;
    if (idx >= total) return;
    const int d = idx % D_DIM;
    const int r = (idx / D_DIM) % NST;
    const int b = idx / (D_DIM * NST);
    const int i1 = NST * ip[0] + 1;
    const float v = (r == i1)
        ? x[((size_t)b * S_LEN + (S_LEN - 1)) * D_DIM + d]
        : state[idx];
    outs[idx] = v;
}

// ---------------------------------------------------------------------------
extern "C" void kernel_launch(void* const* d_in, const int* in_sizes, int n_in,
                              void* d_out, int out_size)
{
    const float* x   = (const float*)d_in[0];
    const float* st  = (const float*)d_in[1];
    const float* tmx = (const float*)d_in[2];
    const float* w1  = (const float*)d_in[3];
    const float* w2  = (const float*)d_in[4];
    const float* mk  = (const float*)d_in[5];
    const float* mw  = (const float*)d_in[6];
    const float* mv  = (const float*)d_in[7];
    const float* mr  = (const float*)d_in[8];
    const float* mg  = (const float*)d_in[9];
    const int*   ip  = (const int*)d_in[10];

    const int B    = in_sizes[0] / (S_LEN * D_DIM);
    const int rows = B * S_LEN;

    float* out       = (float*)d_out;
    float* out_state = out + (size_t)rows * 5 * D_DIM;

    // GEMM1 + tanh (writes g_xxx)
    gemm1_tanh_kernel<<<rows / 64, 256>>>(x, st, tmx, w1, ip);

    // GEMM2 + epilogue (needs >48KB dynamic smem)
    const size_t smem2 = (size_t)(65 * 256 + 32 * 256 + 32 * 65) * sizeof(float);
    cudaFuncSetAttribute(gemm2_epi_kernel,
                         cudaFuncAttributeMaxDynamicSharedMemorySize, (int)smem2);
    dim3 g2(rows / 64, D_DIM / 256);
    gemm2_epi_kernel<<<g2, 256, smem2>>>(x, st, w2, mk, mw, mv, mr, mg, ip, out);

    // new_state
    const int tot = B * NST * D_DIM;
    new_state_kernel<<<(tot + 255) / 256, 256>>>(x, st, ip, out_state, tot);
}

// round 4
// speedup vs baseline: 1.5604x; 1.5604x over previous
#include <cuda_runtime.h>
#include <cstdint>
#include <cstddef>

// RWKV time-mix token-shift block, fp32 with packed f32x2 FMA (sm_103a).
// out = concat(x_kwvrg[B,S,5,D], new_state[B,66,D])

#define S_LEN 2048
#define D_DIM 2048
#define NST   66      // 2 + HEAD_SIZE
#define NL    160     // LoRA width
#define ROWS_MAX 8192

// scratch
__device__ float g_part[2 * ROWS_MAX * NL];   // split-K partials
__device__ float g_xxx[ROWS_MAX * NL];        // tanh(xm @ W1)

// ---- packed fp32 helpers ---------------------------------------------------
__device__ __forceinline__ void ffma2(unsigned long long& d,
                                      unsigned long long a,
                                      unsigned long long b) {
    asm("fma.rn.f32x2 %0, %1, %2, %0;" : "+l"(d) : "l"(a), "l"(b));
}
__device__ __forceinline__ unsigned long long splat2(float v) {
    unsigned long long r;
    unsigned int u = __float_as_uint(v);
    asm("mov.b64 %0, {%1, %1};" : "=l"(r) : "r"(u));
    return r;
}
__device__ __forceinline__ float lo2(unsigned long long v) {
    return __uint_as_float((unsigned int)(v & 0xffffffffull));
}
__device__ __forceinline__ float hi2(unsigned long long v) {
    return __uint_as_float((unsigned int)(v >> 32));
}

// ---------------------------------------------------------------------------
// Kernel 1: fused token-shift mix + GEMM1 partial (split-K=2)
//   xm[r,k] = x[r,k] + (x[r-1,k] - x[r,k]) * tmx[k]   (row -1 -> state[:,i1])
//   g_part[h][r][j] = sum_{k in half h} xm[r,k] * W1[k,j]
// Block: 64 rows x 160 cols, 256 threads. Thread: 8 contiguous rows
// (ty*8..+7, f32x2 row-pairs) x 5 cols. K-tile 16, K-half 1024.
// ---------------------------------------------------------------------------
__global__ __launch_bounds__(256) void gemm1_part_kernel(
    const float* __restrict__ x, const float* __restrict__ state,
    const float* __restrict__ tmx, const float* __restrict__ w1,
    const int* __restrict__ ip)
{
    __shared__ float As[16][64];     // [k][row]
    __shared__ float Bs[16][NL];     // [k][col]

    const int R0 = blockIdx.x * 64;
    const int kc0 = blockIdx.y * 1024;
    const int b  = R0 / S_LEN;
    const int s0 = R0 % S_LEN;
    const int i1 = NST * ip[0] + 1;
    const float* __restrict__ srow = state + ((size_t)b * NST + i1) * D_DIM;

    const int tid = threadIdx.x;
    const int tx  = tid & 31;        // col thread (5 cols: tx+32j)
    const int ty  = tid >> 5;        // row thread (rows ty*8..ty*8+7)
    const int lr  = tid >> 2;        // loader row (0..63)
    const int lk  = (tid & 3) * 4;   // loader k offset (float4)

    unsigned long long acc[4][5];    // f32x2 row-pairs x 5 cols
#pragma unroll
    for (int p = 0; p < 4; p++)
#pragma unroll
        for (int j = 0; j < 5; j++) acc[p][j] = 0ull;

    for (int k0 = kc0; k0 < kc0 + 1024; k0 += 16) {
        // A tile: compute xm on the fly
        {
            const int gr = R0 + lr;
            const float4 cur = *(const float4*)&x[(size_t)gr * D_DIM + k0 + lk];
            float4 prev;
            if (s0 + lr == 0)
                prev = *(const float4*)&srow[k0 + lk];
            else
                prev = *(const float4*)&x[(size_t)(gr - 1) * D_DIM + k0 + lk];
            const float4 t = *(const float4*)&tmx[k0 + lk];
            As[lk + 0][lr] = cur.x + (prev.x - cur.x) * t.x;
            As[lk + 1][lr] = cur.y + (prev.y - cur.y) * t.y;
            As[lk + 2][lr] = cur.z + (prev.z - cur.z) * t.z;
            As[lk + 3][lr] = cur.w + (prev.w - cur.w) * t.w;
        }
        // B tile (float4 vectorized: 16*160 = 640 float4)
#pragma unroll
        for (int l = tid; l < 640; l += 256) {
            const int e  = l * 4;
            const int kk = e / NL, j = e % NL;
            *(float4*)&Bs[kk][j] = *(const float4*)&w1[(size_t)(k0 + kk) * NL + j];
        }
        __syncthreads();

#pragma unroll
        for (int k = 0; k < 16; k++) {
            unsigned long long a2[4], b2[5];
#pragma unroll
            for (int p = 0; p < 4; p++)
                a2[p] = *(const unsigned long long*)&As[k][ty * 8 + 2 * p];
#pragma unroll
            for (int j = 0; j < 5; j++)
                b2[j] = splat2(Bs[k][tx + 32 * j]);
#pragma unroll
            for (int p = 0; p < 4; p++)
#pragma unroll
                for (int j = 0; j < 5; j++)
                    ffma2(acc[p][j], a2[p], b2[j]);
        }
        __syncthreads();
    }

    float* __restrict__ part = g_part + (size_t)blockIdx.y * ROWS_MAX * NL;
#pragma unroll
    for (int p = 0; p < 4; p++) {
        const size_t r0 = (size_t)(R0 + ty * 8 + 2 * p);
#pragma unroll
        for (int j = 0; j < 5; j++) {
            part[r0 * NL + tx + 32 * j]       = lo2(acc[p][j]);
            part[(r0 + 1) * NL + tx + 32 * j] = hi2(acc[p][j]);
        }
    }
}

// ---------------------------------------------------------------------------
// Kernel 1b: reduce split-K halves + tanh  (float4 vectorized)
// ---------------------------------------------------------------------------
__global__ void reduce_tanh_kernel(int n4)
{
    const int i = blockIdx.x * blockDim.x + threadIdx.x;
    if (i >= n4) return;
    const float4 a = ((const float4*)g_part)[i];
    const float4 b = ((const float4*)(g_part + ROWS_MAX * NL))[i];
    float4 o;
    o.x = tanhf(a.x + b.x);
    o.y = tanhf(a.y + b.y);
    o.z = tanhf(a.z + b.z);
    o.w = tanhf(a.w + b.w);
    ((float4*)g_xxx)[i] = o;
}

// ---------------------------------------------------------------------------
// Kernel 2: GEMM2 + epilogue, fused over the 5 modes (f32x2 col-pairs).
//   out[r,f,d] = x[r,d] + sx[r,d] * (maa_f[d] + sum_k xxx[r,f*32+k]*W2[f,k,d])
// Block: 64 rows x 256 d-cols, 256 threads.
// Thread: rows ty*8..+7, cols {tx*4..+3, 128+tx*4..+3}.
// ---------------------------------------------------------------------------
__global__ __launch_bounds__(256, 2) void gemm2_epi_kernel(
    const float* __restrict__ x, const float* __restrict__ state,
    const float* __restrict__ w2,
    const float* __restrict__ mk, const float* __restrict__ mw,
    const float* __restrict__ mv, const float* __restrict__ mr,
    const float* __restrict__ mg,
    const int* __restrict__ ip, float* __restrict__ out)
{
    extern __shared__ float sm[];
    float* xt = sm;                          // [65][256]
    float* Ws = sm + 65 * 256;               // [32][256]
    float* Xs = sm + 65 * 256 + 32 * 256;    // [32][65] (stride 65)

    const int R0 = blockIdx.x * 64;
    const int d0 = blockIdx.y * 256;
    const int b  = R0 / S_LEN;
    const int s0 = R0 % S_LEN;
    const int i1 = NST * ip[0] + 1;
    const float* __restrict__ srow = state + ((size_t)b * NST + i1) * D_DIM;

    const int tid = threadIdx.x;
    const int tx  = tid & 31;
    const int ty  = tid >> 5;
    const int c0  = tx * 4;          // first col group
    const int c1  = 128 + tx * 4;    // second col group

    // x tile: rows R0-1 .. R0+63 (row -1 from state when s0==0), float4 loads
    for (int l4 = tid; l4 < 65 * 64; l4 += 256) {
        const int rr = l4 >> 6, dd = (l4 & 63) * 4;
        float4 v;
        if (rr == 0)
            v = (s0 == 0) ? *(const float4*)&srow[d0 + dd]
                          : *(const float4*)&x[(size_t)(R0 - 1) * D_DIM + d0 + dd];
        else
            v = *(const float4*)&x[(size_t)(R0 + rr - 1) * D_DIM + d0 + dd];
        *(float4*)&xt[rr * 256 + dd] = v;
    }

    for (int f = 0; f < 5; ++f) {
        __syncthreads();   // xt ready (f==0) / all warps past Ws/Xs reads (f>0)
        // W2 tile: [32][256] float4
        for (int l4 = tid; l4 < 2048; l4 += 256) {
            const int kk = l4 >> 6, dd = (l4 & 63) * 4;
            *(float4*)&Ws[kk * 256 + dd] =
                *(const float4*)&w2[((size_t)f * 32 + kk) * D_DIM + d0 + dd];
        }
        // xxx tile: Xs[k][row], stride 65 (conflict-free STS)
        for (int l = tid; l < 64 * 32; l += 256) {
            const int kk = l & 31, rr = l >> 5;
            Xs[kk * 65 + rr] = g_xxx[(size_t)(R0 + rr) * NL + f * 32 + kk];
        }
        __syncthreads();

        unsigned long long acc[8][4];   // [row][col-pair]
#pragma unroll
        for (int i = 0; i < 8; i++)
#pragma unroll
            for (int j = 0; j < 4; j++) acc[i][j] = 0ull;

#pragma unroll 4
        for (int k = 0; k < 32; k++) {
            const ulonglong2 wA = *(const ulonglong2*)&Ws[k * 256 + c0];
            const ulonglong2 wB = *(const ulonglong2*)&Ws[k * 256 + c1];
            unsigned long long a2[8];
#pragma unroll
            for (int ri = 0; ri < 8; ri++)
                a2[ri] = splat2(Xs[k * 65 + ty * 8 + ri]);
#pragma unroll
            for (int ri = 0; ri < 8; ri++) {
                ffma2(acc[ri][0], a2[ri], wA.x);
                ffma2(acc[ri][1], a2[ri], wA.y);
                ffma2(acc[ri][2], a2[ri], wB.x);
                ffma2(acc[ri][3], a2[ri], wB.y);
            }
        }

        const float* __restrict__ maa =
            (f == 0) ? mk : (f == 1) ? mw : (f == 2) ? mv : (f == 3) ? mr : mg;
        const float4 mA = *(const float4*)&maa[d0 + c0];
        const float4 mB = *(const float4*)&maa[d0 + c1];

        float4 pA = *(const float4*)&xt[(ty * 8) * 256 + c0];   // row r-1
        float4 pB = *(const float4*)&xt[(ty * 8) * 256 + c1];
#pragma unroll
        for (int ri = 0; ri < 8; ri++) {
            const int r = ty * 8 + ri;
            const float4 cA = *(const float4*)&xt[(r + 1) * 256 + c0];
            const float4 cB = *(const float4*)&xt[(r + 1) * 256 + c1];
            float4 oA, oB;
            oA.x = cA.x + (pA.x - cA.x) * (mA.x + lo2(acc[ri][0]));
            oA.y = cA.y + (pA.y - cA.y) * (mA.y + hi2(acc[ri][0]));
            oA.z = cA.z + (pA.z - cA.z) * (mA.z + lo2(acc[ri][1]));
            oA.w = cA.w + (pA.w - cA.w) * (mA.w + hi2(acc[ri][1]));
            oB.x = cB.x + (pB.x - cB.x) * (mB.x + lo2(acc[ri][2]));
            oB.y = cB.y + (pB.y - cB.y) * (mB.y + hi2(acc[ri][2]));
            oB.z = cB.z + (pB.z - cB.z) * (mB.z + lo2(acc[ri][3]));
            oB.w = cB.w + (pB.w - cB.w) * (mB.w + hi2(acc[ri][3]));
            float* __restrict__ op =
                out + ((size_t)(R0 + r) * 5 + f) * D_DIM + d0;
            *(float4*)&op[c0] = oA;
            *(float4*)&op[c1] = oB;
            pA = cA; pB = cB;
        }
    }
}

// ---------------------------------------------------------------------------
// Kernel 3: new_state = state with row i1 := x[:, S-1, :]
// ---------------------------------------------------------------------------
__global__ void new_state_kernel(
    const float* __restrict__ x, const float* __restrict__ state,
    const int* __restrict__ ip, float* __restrict__ outs, int total4)
{
    const int idx = blockIdx.x * blockDim.x + threadIdx.x;
    if (idx >= total4) return;
    const int e = idx * 4;
    const int d = e % D_DIM;
    const int r = (e / D_DIM) % NST;
    const int b = e / (D_DIM * NST);
    const int i1 = NST * ip[0] + 1;
    float4 v;
    if (r == i1)
        v = *(const float4*)&x[((size_t)b * S_LEN + (S_LEN - 1)) * D_DIM + d];
    else
        v = *(const float4*)&state[e];
    *(float4*)&outs[e] = v;
}

// ---------------------------------------------------------------------------
extern "C" void kernel_launch(void* const* d_in, const int* in_sizes, int n_in,
                              void* d_out, int out_size)
{
    const float* x   = (const float*)d_in[0];
    const float* st  = (const float*)d_in[1];
    const float* tmx = (const float*)d_in[2];
    const float* w1  = (const float*)d_in[3];
    const float* w2  = (const float*)d_in[4];
    const float* mk  = (const float*)d_in[5];
    const float* mw  = (const float*)d_in[6];
    const float* mv  = (const float*)d_in[7];
    const float* mr  = (const float*)d_in[8];
    const float* mg  = (const float*)d_in[9];
    const int*   ip  = (const int*)d_in[10];

    const int B    = in_sizes[0] / (S_LEN * D_DIM);
    const int rows = B * S_LEN;

    float* out       = (float*)d_out;
    float* out_state = out + (size_t)rows * 5 * D_DIM;

    // GEMM1 split-K partials
    dim3 g1(rows / 64, 2);
    gemm1_part_kernel<<<g1, 256>>>(x, st, tmx, w1, ip);

    // reduce + tanh
    const int n4 = rows * NL / 4;
    reduce_tanh_kernel<<<(n4 + 255) / 256, 256>>>(n4);

    // GEMM2 + epilogue
    const size_t smem2 = (size_t)(65 * 256 + 32 * 256 + 32 * 65) * sizeof(float);
    cudaFuncSetAttribute(gemm2_epi_kernel,
                         cudaFuncAttributeMaxDynamicSharedMemorySize, (int)smem2);
    dim3 g2(rows / 64, D_DIM / 256);
    gemm2_epi_kernel<<<g2, 256, smem2>>>(x, st, w2, mk, mw, mv, mr, mg, ip, out);

    // new_state
    const int tot4 = B * NST * D_DIM / 4;
    new_state_kernel<<<(tot4 + 255) / 256, 256>>>(x, st, ip, out_state, tot4);
}

// round 6
// speedup vs baseline: 1.8326x; 1.1745x over previous
#include <cuda_runtime.h>
#include <cuda_bf16.h>
#include <cstdint>
#include <cstddef>

// RWKV time-mix token-shift block — bf16 HMMA (mma.sync) for both GEMMs.
// out = concat(x_kwvrg[B,S,5,D], new_state[B,66,D])

#define S_LEN 2048
#define D_DIM 2048
#define NST   66
#define NL    160
#define ROWS_MAX 8192

// scratch
__device__ __nv_bfloat16 g_xxxh[ROWS_MAX * NL];      // tanh(xm@W1), bf16
__device__ __nv_bfloat16 g_w1t[NL * D_DIM];          // W1^T [n][k] bf16
__device__ __nv_bfloat16 g_w2t[5 * D_DIM * 32];      // W2^T [f][d][k] bf16

// ---- mma.sync bf16 (m16n8k16, row.col, f32 accum) --------------------------
__device__ __forceinline__ void mma_bf16(float* c,
                                         uint32_t a0, uint32_t a1,
                                         uint32_t a2, uint32_t a3,
                                         uint32_t b0, uint32_t b1) {
    asm volatile(
        "mma.sync.aligned.m16n8k16.row.col.f32.bf16.bf16.f32 "
        "{%0,%1,%2,%3}, {%4,%5,%6,%7}, {%8,%9}, {%0,%1,%2,%3};"
        : "+f"(c[0]), "+f"(c[1]), "+f"(c[2]), "+f"(c[3])
        : "r"(a0), "r"(a1), "r"(a2), "r"(a3), "r"(b0), "r"(b1));
}

__device__ __forceinline__ uint32_t bf2_pack(float lo, float hi) {
    __nv_bfloat162 h = __floats2bfloat162_rn(lo, hi);
    return *(uint32_t*)&h;
}

// ---------------------------------------------------------------------------
// Prep: W1[2048][160] f32 -> g_w1t[160][2048] bf16
// ---------------------------------------------------------------------------
__global__ void w1t_kernel(const float* __restrict__ w1)
{
    __shared__ float t[32][33];
    const int k0 = blockIdx.x * 32;
    const int n0 = blockIdx.y * 32;
    const int tid = threadIdx.x;
    for (int l = tid; l < 1024; l += 256) {
        const int kk = l >> 5, nn = l & 31;
        t[kk][nn] = w1[(size_t)(k0 + kk) * NL + n0 + nn];
    }
    __syncthreads();
    const int nn = tid >> 3;
    const int kc = (tid & 7) * 4;
    uint2 pk;
    pk.x = bf2_pack(t[kc + 0][nn], t[kc + 1][nn]);
    pk.y = bf2_pack(t[kc + 2][nn], t[kc + 3][nn]);
    *(uint2*)&g_w1t[(size_t)(n0 + nn) * D_DIM + k0 + kc] = pk;
}

// ---------------------------------------------------------------------------
// Prep: W2[5][32][2048] f32 -> g_w2t[f][d][k] bf16
// ---------------------------------------------------------------------------
__global__ void w2t_kernel(const float* __restrict__ w2)
{
    __shared__ float t[32][33];
    const int f  = blockIdx.y;
    const int d0 = blockIdx.x * 32;
    const int tid = threadIdx.x;
    for (int l = tid; l < 1024; l += 256) {
        const int kk = l >> 5, dd = l & 31;
        t[kk][dd] = w2[((size_t)f * 32 + kk) * D_DIM + d0 + dd];
    }
    __syncthreads();
    const int dd = tid >> 3;
    const int kc = (tid & 7) * 4;
    uint2 pk;
    pk.x = bf2_pack(t[kc + 0][dd], t[kc + 1][dd]);
    pk.y = bf2_pack(t[kc + 2][dd], t[kc + 3][dd]);
    *(uint2*)&g_w2t[(((size_t)f * D_DIM) + d0 + dd) * 32 + kc] = pk;
}

// ---------------------------------------------------------------------------
// GEMM1: xm = x + (prev - x)*tmx;  g_xxxh = bf16(tanh(xm @ W1))
// CTA: 32 rows x 160 cols, 8 warps (2m x 4n), warp tile 16x40. K chunks of 64.
// smem stride 72 bf16 (144B): STS.128 + frag LDS conflict-free.
// ---------------------------------------------------------------------------
__global__ __launch_bounds__(256) void gemm1_mma_kernel(
    const float* __restrict__ x, const float* __restrict__ state,
    const float* __restrict__ tmx, const int* __restrict__ ip)
{
    __shared__ __nv_bfloat16 As[32][72];    // xm tile [r][k]
    __shared__ __nv_bfloat16 Bs[NL][72];    // W1^T tile [n][k]

    const int R0 = blockIdx.x * 32;
    const int b  = R0 / S_LEN;
    const int s0 = R0 % S_LEN;
    const int i1 = NST * ip[0] + 1;
    const float* __restrict__ srow = state + ((size_t)b * NST + i1) * D_DIM;

    const int tid  = threadIdx.x;
    const int w    = tid >> 5;
    const int lane = tid & 31;
    const int g    = lane >> 2;
    const int tg   = lane & 3;
    const int mb   = (w >> 2) * 16;     // warp row base (0 or 16)
    const int nb   = (w & 3) * 40;      // warp col base

    // loader role
    const int lr = tid >> 3;            // row 0..31
    const int lk = (tid & 7) * 8;       // k offset (8 elements)
    const int glr = R0 + lr;
    const float* __restrict__ curp = x + (size_t)glr * D_DIM;
    const float* __restrict__ prvp = (s0 == 0 && lr == 0)
        ? srow : x + (size_t)(glr - 1) * D_DIM;

    float acc[5][4];
#pragma unroll
    for (int j = 0; j < 5; j++)
#pragma unroll
        for (int q = 0; q < 4; q++) acc[j][q] = 0.0f;

    for (int k0 = 0; k0 < D_DIM; k0 += 64) {
        __syncthreads();
        // A tile: compute xm (fp32) -> bf16
        {
            const float4 c0 = *(const float4*)&curp[k0 + lk];
            const float4 c1 = *(const float4*)&curp[k0 + lk + 4];
            const float4 p0 = *(const float4*)&prvp[k0 + lk];
            const float4 p1 = *(const float4*)&prvp[k0 + lk + 4];
            const float4 t0 = *(const float4*)&tmx[k0 + lk];
            const float4 t1 = *(const float4*)&tmx[k0 + lk + 4];
            uint4 v;
            v.x = bf2_pack(c0.x + (p0.x - c0.x) * t0.x,
                           c0.y + (p0.y - c0.y) * t0.y);
            v.y = bf2_pack(c0.z + (p0.z - c0.z) * t0.z,
                           c0.w + (p0.w - c0.w) * t0.w);
            v.z = bf2_pack(c1.x + (p1.x - c1.x) * t1.x,
                           c1.y + (p1.y - c1.y) * t1.y);
            v.w = bf2_pack(c1.z + (p1.z - c1.z) * t1.z,
                           c1.w + (p1.w - c1.w) * t1.w);
            *(uint4*)&As[lr][lk] = v;
        }
        // B tile: g_w1t rows 0..159, k0..k0+63
#pragma unroll
        for (int l = tid; l < NL * 8; l += 256) {
            const int n = l >> 3, kg = (l & 7) * 8;
            *(uint4*)&Bs[n][kg] = *(const uint4*)&g_w1t[(size_t)n * D_DIM + k0 + kg];
        }
        __syncthreads();

#pragma unroll
        for (int ks = 0; ks < 4; ks++) {
            const int ko = ks * 16 + tg * 2;
            const uint32_t a0 = *(const uint32_t*)&As[mb + g][ko];
            const uint32_t a1 = *(const uint32_t*)&As[mb + g + 8][ko];
            const uint32_t a2 = *(const uint32_t*)&As[mb + g][ko + 8];
            const uint32_t a3 = *(const uint32_t*)&As[mb + g + 8][ko + 8];
#pragma unroll
            for (int j = 0; j < 5; j++) {
                const int n = nb + j * 8 + g;
                const uint32_t b0 = *(const uint32_t*)&Bs[n][ko];
                const uint32_t b1 = *(const uint32_t*)&Bs[n][ko + 8];
                mma_bf16(acc[j], a0, a1, a2, a3, b0, b1);
            }
        }
    }

    // epilogue: tanh -> bf16 store
#pragma unroll
    for (int j = 0; j < 5; j++) {
        const int col = nb + j * 8 + tg * 2;
        const size_t rlo = (size_t)(R0 + mb + g) * NL + col;
        const size_t rhi = (size_t)(R0 + mb + g + 8) * NL + col;
        *(uint32_t*)&g_xxxh[rlo] = bf2_pack(tanhf(acc[j][0]), tanhf(acc[j][1]));
        *(uint32_t*)&g_xxxh[rhi] = bf2_pack(tanhf(acc[j][2]), tanhf(acc[j][3]));
    }
}

// ---------------------------------------------------------------------------
// GEMM2 + epilogue: out[r,f,d] = cur + (prev-cur)*(maa_f[d] + xxx_f @ W2_f)
// CTA: 32 rows x 128 d, 8 warps (2m x 4d), warp m16 x d32 (4 n-tiles).
// Mode loop innermost: cur/prev held in registers across all 5 modes.
// ---------------------------------------------------------------------------
__global__ __launch_bounds__(256) void gemm2_mma_kernel(
    const float* __restrict__ x, const float* __restrict__ state,
    const float* __restrict__ mk, const float* __restrict__ mw,
    const float* __restrict__ mv, const float* __restrict__ mr,
    const float* __restrict__ mg,
    const int* __restrict__ ip, float* __restrict__ out)
{
    const int R0 = blockIdx.x * 32;
    const int d0 = blockIdx.y * 128;
    const int b  = R0 / S_LEN;
    const int s0 = R0 % S_LEN;
    const int i1 = NST * ip[0] + 1;
    const float* __restrict__ srow = state + ((size_t)b * NST + i1) * D_DIM;

    const int tid  = threadIdx.x;
    const int w    = tid >> 5;
    const int lane = tid & 31;
    const int g    = lane >> 2;
    const int tg   = lane & 3;
    const int mb   = (w >> 2) * 16;        // warp row base
    const int db   = d0 + (w & 3) * 32;    // warp d base

    const int r_lo = R0 + mb + g;          // global rows
    const int r_hi = r_lo + 8;
    const float* __restrict__ curL = x + (size_t)r_lo * D_DIM + db;
    const float* __restrict__ curH = x + (size_t)r_hi * D_DIM + db;
    const float* __restrict__ prvL = (s0 == 0 && mb + g == 0)
        ? srow + db : curL - D_DIM;
    const float* __restrict__ prvH = curH - D_DIM;

    // load cur/prev once (held across the 5 modes)
    float2 cl[4], ch[4], pl[4], ph[4];
#pragma unroll
    for (int j = 0; j < 4; j++) {
        const int c = j * 8 + tg * 2;
        cl[j] = *(const float2*)&curL[c];
        ch[j] = *(const float2*)&curH[c];
        pl[j] = *(const float2*)&prvL[c];
        ph[j] = *(const float2*)&prvH[c];
    }

    const __nv_bfloat16* __restrict__ aL = g_xxxh + (size_t)r_lo * NL;
    const __nv_bfloat16* __restrict__ aH = g_xxxh + (size_t)r_hi * NL;

#pragma unroll
    for (int f = 0; f < 5; f++) {
        const float* __restrict__ maa =
            (f == 0) ? mk : (f == 1) ? mw : (f == 2) ? mv : (f == 3) ? mr : mg;

        float acc[4][4];
#pragma unroll
        for (int j = 0; j < 4; j++)
#pragma unroll
            for (int q = 0; q < 4; q++) acc[j][q] = 0.0f;

#pragma unroll
        for (int ks = 0; ks < 2; ks++) {
            const int ko = f * 32 + ks * 16 + tg * 2;
            const uint32_t a0 = *(const uint32_t*)&aL[ko];
            const uint32_t a1 = *(const uint32_t*)&aH[ko];
            const uint32_t a2 = *(const uint32_t*)&aL[ko + 8];
            const uint32_t a3 = *(const uint32_t*)&aH[ko + 8];
#pragma unroll
            for (int j = 0; j < 4; j++) {
                const __nv_bfloat16* bp =
                    g_w2t + (((size_t)f * D_DIM) + db + j * 8 + g) * 32
                          + ks * 16 + tg * 2;
                const uint32_t b0 = *(const uint32_t*)bp;
                const uint32_t b1 = *(const uint32_t*)(bp + 8);
                mma_bf16(acc[j], a0, a1, a2, a3, b0, b1);
            }
        }

        float* __restrict__ oL = out + ((size_t)r_lo * 5 + f) * D_DIM + db;
        float* __restrict__ oH = out + ((size_t)r_hi * 5 + f) * D_DIM + db;
#pragma unroll
        for (int j = 0; j < 4; j++) {
            const int c = j * 8 + tg * 2;
            const float2 mm = *(const float2*)&maa[db + c];
            float2 olo, ohi;
            olo.x = cl[j].x + (pl[j].x - cl[j].x) * (mm.x + acc[j][0]);
            olo.y = cl[j].y + (pl[j].y - cl[j].y) * (mm.y + acc[j][1]);
            ohi.x = ch[j].x + (ph[j].x - ch[j].x) * (mm.x + acc[j][2]);
            ohi.y = ch[j].y + (ph[j].y - ch[j].y) * (mm.y + acc[j][3]);
            *(float2*)&oL[c] = olo;
            *(float2*)&oH[c] = ohi;
        }
    }
}

// ---------------------------------------------------------------------------
// new_state = state with row i1 := x[:, S-1, :]
// ---------------------------------------------------------------------------
__global__ void new_state_kernel(
    const float* __restrict__ x, const float* __restrict__ state,
    const int* __restrict__ ip, float* __restrict__ outs, int total4)
{
    const int idx = blockIdx.x * blockDim.x + threadIdx.x;
    if (idx >= total4) return;
    const int e = idx * 4;
    const int d = e % D_DIM;
    const int r = (e / D_DIM) % NST;
    const int b = e / (D_DIM * NST);
    const int i1 = NST * ip[0] + 1;
    float4 v;
    if (r == i1)
        v = *(const float4*)&x[((size_t)b * S_LEN + (S_LEN - 1)) * D_DIM + d];
    else
        v = *(const float4*)&state[e];
    *(float4*)&outs[e] = v;
}

// ---------------------------------------------------------------------------
extern "C" void kernel_launch(void* const* d_in, const int* in_sizes, int n_in,
                              void* d_out, int out_size)
{
    const float* x   = (const float*)d_in[0];
    const float* st  = (const float*)d_in[1];
    const float* tmx = (const float*)d_in[2];
    const float* w1  = (const float*)d_in[3];
    const float* w2  = (const float*)d_in[4];
    const float* mk  = (const float*)d_in[5];
    const float* mw  = (const float*)d_in[6];
    const float* mv  = (const float*)d_in[7];
    const float* mr  = (const float*)d_in[8];
    const float* mg  = (const float*)d_in[9];
    const int*   ip  = (const int*)d_in[10];

    const int B    = in_sizes[0] / (S_LEN * D_DIM);
    const int rows = B * S_LEN;

    float* out       = (float*)d_out;
    float* out_state = out + (size_t)rows * 5 * D_DIM;

    // weight transposes (bf16)
    dim3 gw1(D_DIM / 32, NL / 32);
    w1t_kernel<<<gw1, 256>>>(w1);
    dim3 gw2(D_DIM / 32, 5);
    w2t_kernel<<<gw2, 256>>>(w2);

    // GEMM1 (HMMA) + tanh -> g_xxxh
    gemm1_mma_kernel<<<rows / 32, 256>>>(x, st, tmx, ip);

    // GEMM2 (HMMA) + fused epilogue
    dim3 g2(rows / 32, D_DIM / 128);
    gemm2_mma_kernel<<<g2, 256>>>(x, st, mk, mw, mv, mr, mg, ip, out);

    // new_state
    const int tot4 = B * NST * D_DIM / 4;
    new_state_kernel<<<(tot4 + 255) / 256, 256>>>(x, st, ip, out_state, tot4);
}